// round 16
// baseline (speedup 1.0000x reference)
#include <cuda_runtime.h>
#include <cuda_fp16.h>

// OhemMSELoss: loss = w*(p-t)^2 / 2^25 over N=2^25; mean of top-k (k=2^18).
// Sample-first, no-scratch pipeline:
// K0: 1/64 cluster sample of inputs (6 MB) -> sampled hist -> LAST BLOCK
//     (ticket) computes conservative threshold T0 (9-sigma margin); zeroes
//     g_hist64; cleans sample hist.
// K1: ONE full streaming pass (402 MB): loss -> SINGLE per-iteration early-out
//     (7 vmax + 1 vcmp over 16 elems, taken ~13%) -> rare path tests halfwords
//     into exact 64K-bin hist; LAST BLOCK (ticket) finalizes (fp32 scans).

#define N_ELEM   33554432
#define N4       (N_ELEM / 4)       // 8388608 float4 per input stream
#define K_KEPT   262144u
#define MARGIN   40960u
#define NSB      4096
#define NREP     8
#define NTILES   512                // sampled tiles (256 float4 each) = 1/64

static __device__ unsigned  g_shist[NREP][NSB];       // zero-init; cleaned by K0
static __device__ unsigned  g_hist64[65536];          // zeroed by K0
static __device__ unsigned  g_T0;
static __device__ unsigned  g_ticketA;                // zero-init; reset by K0
static __device__ unsigned  g_ticketB;                // zero-init; reset by K1

__device__ __forceinline__ float bin_valf(int b) {
    return __half2float(__ushort_as_half((unsigned short)b));
}

// loss for 4 elems -> 2 packed fp16 words (sub+mul+mul only).
__device__ __forceinline__ uint2 loss4(float4 pv, float4 tv, float4 wv) {
    float d0 = pv.x - tv.x, d1 = pv.y - tv.y;
    float d2 = pv.z - tv.z, d3 = pv.w - tv.w;
    __half2 h0 = __floats2half2_rn(wv.x * d0 * d0, wv.y * d1 * d1);
    __half2 h1 = __floats2half2_rn(wv.z * d2 * d2, wv.w * d3 * d3);
    uint2 o;
    o.x = *reinterpret_cast<unsigned*>(&h0);
    o.y = *reinterpret_cast<unsigned*>(&h1);
    return o;
}

// ---------------------------------------------------------------- K0: sample + select
// grid 148 x 256. Reads 512 tiles x 1KB x 3 streams = 6 MB (coalesced).
__global__ __launch_bounds__(256) void k_sample(
    const float4* __restrict__ p,
    const float4* __restrict__ t,
    const float4* __restrict__ w)
{
    if (blockIdx.x < 64)                               // zero hist64 (256 KB)
        reinterpret_cast<uint4*>(g_hist64)[blockIdx.x * 256 + threadIdx.x] =
            make_uint4(0, 0, 0, 0);

    unsigned* hist = g_shist[blockIdx.x & (NREP - 1)];

    // 1/64 cluster sample: tile j covers float4s [j*16384, j*16384+256)
    for (int tile = blockIdx.x; tile < NTILES; tile += gridDim.x) {
        const int f = tile * 16384 + threadIdx.x;
        float4 pv = __ldg(p + f), tv = __ldg(t + f), wv = __ldg(w + f);
        uint2 o = loss4(pv, tv, wv);
        atomicAdd(&hist[(o.x & 0xFFFFu) >> 4], 1u);    // all 4 elements counted
        atomicAdd(&hist[ o.x >> 20        ], 1u);
        atomicAdd(&hist[(o.y & 0xFFFFu) >> 4], 1u);
        atomicAdd(&hist[ o.y >> 20        ], 1u);
    }

    // ---- last-block election ----
    __shared__ bool s_last;
    __syncthreads();
    if (threadIdx.x == 0) {
        __threadfence();
        s_last = (atomicAdd(&g_ticketA, 1u) == gridDim.x - 1u);
    }
    __syncthreads();
    if (!s_last) return;
    __threadfence();

    // ---- fused select (256 threads): conservative threshold T0 from sample ----
    __shared__ unsigned chunk[256];
    const int t0 = threadIdx.x;
    unsigned bl[16];
    #pragma unroll
    for (int j = 0; j < 16; j++) bl[j] = 0u;
    #pragma unroll
    for (int r = 0; r < NREP; r++) {
        const uint4* row = reinterpret_cast<const uint4*>(&g_shist[r][t0 * 16]);
        #pragma unroll
        for (int q = 0; q < 4; q++) {
            uint4 v = row[q];
            bl[q*4+0] += v.x; bl[q*4+1] += v.y; bl[q*4+2] += v.z; bl[q*4+3] += v.w;
        }
    }
    #pragma unroll
    for (int r = 0; r < NREP; r++) {                  // self-clean sample hist
        uint4* row = reinterpret_cast<uint4*>(&g_shist[r][t0 * 16]);
        #pragma unroll
        for (int q = 0; q < 4; q++) row[q] = make_uint4(0, 0, 0, 0);
    }
    unsigned csum = 0;
    #pragma unroll
    for (int j = 0; j < 16; j++) csum += bl[j];
    chunk[t0] = csum;
    __syncthreads();
    for (int d = 1; d < 256; d <<= 1) {               // suffix scan over chunks
        unsigned v = chunk[t0];
        if (t0 + d < 256) v += chunk[t0 + d];
        __syncthreads();
        chunk[t0] = v;
        __syncthreads();
    }
    const unsigned TGT = (K_KEPT + MARGIN + 63u) / 64u;   // sampled-count target
    unsigned sufnext = (t0 < 255) ? chunk[t0 + 1] : 0u;
    if (chunk[t0] >= TGT && sufnext < TGT) {
        unsigned cum = sufnext, T0v = 0;
        for (int b = 15; b >= 0; b--) {
            cum += bl[b];
            if (cum >= TGT) { T0v = ((unsigned)(t0 * 16 + b)) << 4; break; }
        }
        g_T0 = T0v;
        g_ticketA = 0u;                               // reset for next replay
    }
}

// ---------------------------------------------------------------- K1: full pass (+fused finalize)
// grid MUST be 1024 x 256: N4/(4*T) == 8 exact trips, lane-consecutive indices.
__global__ __launch_bounds__(256) void k_main(
    const float4* __restrict__ p,
    const float4* __restrict__ t,
    const float4* __restrict__ w,
    float* __restrict__ out)
{
    const unsigned thr = g_T0;
    const unsigned TT  = thr | (thr << 16);
    const int T = gridDim.x * blockDim.x;             // 262144

    #define TESTW(u) do {                                                       \
        unsigned _a = (u) & 0xFFFFu, _b = (u) >> 16;                            \
        if (_a >= thr) atomicAdd(&g_hist64[_a], 1u);                            \
        if (_b >= thr) atomicAdd(&g_hist64[_b], 1u);                            \
    } while (0)

    for (int f = blockIdx.x * blockDim.x + threadIdx.x; f < N4; f += 4 * T) {
        const int f1 = f + T, f2 = f + 2 * T, f3 = f + 3 * T;
        // 12 independent, perfectly-coalesced LDG.128 (evict-first)
        float4 pa = __ldcs(p + f),  ta = __ldcs(t + f),  wa = __ldcs(w + f);
        float4 pb = __ldcs(p + f1), tb = __ldcs(t + f1), wb = __ldcs(w + f1);
        float4 pc = __ldcs(p + f2), tc = __ldcs(t + f2), wc = __ldcs(w + f2);
        float4 pd = __ldcs(p + f3), td = __ldcs(t + f3), wd = __ldcs(w + f3);

        uint2 oa = loss4(pa, ta, wa);
        uint2 ob = loss4(pb, tb, wb);
        uint2 oc = loss4(pc, tc, wc);
        uint2 od = loss4(pd, td, wd);

        // ONE early-out over all 16 elements (7 vmax + 1 vcmp); taken ~13%
        unsigned m = __vmaxu2(
            __vmaxu2(__vmaxu2(oa.x, oa.y), __vmaxu2(ob.x, ob.y)),
            __vmaxu2(__vmaxu2(oc.x, oc.y), __vmaxu2(od.x, od.y)));
        if (__vcmpgeu2(m, TT)) {
            TESTW(oa.x); TESTW(oa.y);
            TESTW(ob.x); TESTW(ob.y);
            TESTW(oc.x); TESTW(oc.y);
            TESTW(od.x); TESTW(od.y);
        }
    }
    #undef TESTW

    // ---- last-block election ----
    __shared__ bool s_last;
    __syncthreads();
    if (threadIdx.x == 0) {
        __threadfence();
        s_last = (atomicAdd(&g_ticketB, 1u) == gridDim.x - 1u);
    }
    __syncthreads();
    if (!s_last) return;
    __threadfence();

    // ---- fused finalize (256 threads, fp32, all L2-hot) ----
    __shared__ unsigned sc[256];
    __shared__ float    sw[256];
    __shared__ int      s_chunk;
    __shared__ unsigned s_ac;
    __shared__ float    s_aw;
    const int tx = threadIdx.x;
    const uint4* h4 = reinterpret_cast<const uint4*>(g_hist64);

    unsigned cnt = 0; float ws = 0.0f;                // thread tx: bins [256tx, 256tx+256)
    #pragma unroll 8
    for (int jj = 0; jj < 64; jj++) {
        uint4 v = h4[tx * 64 + jj];
        int b = tx * 256 + jj * 4;
        cnt += v.x + v.y + v.z + v.w;
        if (v.x) ws += (float)v.x * bin_valf(b + 0);
        if (v.y) ws += (float)v.y * bin_valf(b + 1);
        if (v.z) ws += (float)v.z * bin_valf(b + 2);
        if (v.w) ws += (float)v.w * bin_valf(b + 3);
    }
    sc[tx] = cnt; sw[tx] = ws;
    if (tx == 0) s_chunk = -1;
    __syncthreads();
    for (int d = 1; d < 256; d <<= 1) {               // suffix scan over 256 chunks
        unsigned cx = sc[tx]; float xx = sw[tx];
        if (tx + d < 256) { cx += sc[tx + d]; xx += sw[tx + d]; }
        __syncthreads();
        sc[tx] = cx; sw[tx] = xx;
        __syncthreads();
    }
    unsigned cn = (tx < 255) ? sc[tx + 1] : 0u;
    float    wn = (tx < 255) ? sw[tx + 1] : 0.0f;
    if (sc[tx] >= K_KEPT && cn < K_KEPT) { s_chunk = tx; s_ac = cn; s_aw = wn; }
    __syncthreads();

    const int chunk = s_chunk;
    if (chunk < 0) {                                  // margin failure (~9-sigma; ~never)
        if (tx == 0) {
            float acc = sw[0] + (float)(K_KEPT - sc[0]) * bin_valf((int)thr);
            out[0] = acc / 8796093022208.0f;          // / 2^43
        }
    } else {
        __syncthreads();
        unsigned bc = g_hist64[chunk * 256 + tx];     // L2-hot
        sc[tx] = bc;
        sw[tx] = bc ? (float)bc * bin_valf(chunk * 256 + tx) : 0.0f;
        __syncthreads();
        for (int d = 1; d < 256; d <<= 1) {           // suffix scan within chunk
            unsigned cx = sc[tx]; float xx = sw[tx];
            if (tx + d < 256) { cx += sc[tx + d]; xx += sw[tx + d]; }
            __syncthreads();
            sc[tx] = cx; sw[tx] = xx;
            __syncthreads();
        }
        unsigned bn = (tx < 255) ? sc[tx + 1] : 0u;
        float    bw = (tx < 255) ? sw[tx + 1] : 0.0f;
        unsigned above = s_ac + bn;
        if (s_ac + sc[tx] >= K_KEPT && above < K_KEPT) {
            unsigned r = K_KEPT - above;
            float acc = s_aw + bw + (float)r * bin_valf(chunk * 256 + tx);
            out[0] = acc / 8796093022208.0f;          // / (2^25 * 2^18)
        }
    }
    if (tx == 0) g_ticketB = 0u;                      // reset for next replay
}

// ---------------------------------------------------------------- launch
extern "C" void kernel_launch(void* const* d_in, const int* in_sizes, int n_in,
                              void* d_out, int out_size) {
    const float4* p = (const float4*)d_in[0];   // predict
    const float4* t = (const float4*)d_in[1];   // target
    const float4* w = (const float4*)d_in[2];   // weight
    float* out = (float*)d_out;

    k_sample<<<148, 256>>>(p, t, w);        // 6 MB sample -> T0
    k_main  <<<1024, 256>>>(p, t, w, out);  // grid MUST stay 1024 (exact trips)
}

// round 17
// speedup vs baseline: 1.2412x; 1.2412x over previous
#include <cuda_runtime.h>
#include <cuda_fp16.h>

// OhemMSELoss: loss = w*(p-t)^2 / 2^25 over N=2^25; mean of top-k (k=2^18).
// Sample-first, no-scratch pipeline:
// K0: 1/64 cluster sample of inputs (6 MB) -> sampled hist -> LAST BLOCK
//     (ticket) computes conservative threshold T0 (9-sigma margin); zeroes
//     g_hist64; cleans sample hist.
// K1: ONE full streaming pass (402 MB): loss -> per-halfword test via
//     HAND-PREDICATED red.global (setp + @p red -- NO BSSY/BSYNC envelopes,
//     the pattern ptxas refuses to emit from C++ if{}); exact 64K-bin hist;
//     LAST BLOCK (ticket) finalizes: fp32 suffix scans -> exact top-k mean.

#define N_ELEM   33554432
#define N4       (N_ELEM / 4)       // 8388608 float4 per input stream
#define K_KEPT   262144u
#define MARGIN   40960u
#define NSB      4096
#define NREP     8
#define NTILES   512                // sampled tiles (256 float4 each) = 1/64

static __device__ unsigned  g_shist[NREP][NSB];       // zero-init; cleaned by K0
static __device__ unsigned  g_hist64[65536];          // zeroed by K0
static __device__ unsigned  g_T0;
static __device__ unsigned  g_ticketA;                // zero-init; reset by K0
static __device__ unsigned  g_ticketB;                // zero-init; reset by K1

__device__ __forceinline__ float bin_valf(int b) {
    return __half2float(__ushort_as_half((unsigned short)b));
}

// loss for 4 elems -> 2 packed fp16 words (sub+mul+mul only).
__device__ __forceinline__ uint2 loss4(float4 pv, float4 tv, float4 wv) {
    float d0 = pv.x - tv.x, d1 = pv.y - tv.y;
    float d2 = pv.z - tv.z, d3 = pv.w - tv.w;
    __half2 h0 = __floats2half2_rn(wv.x * d0 * d0, wv.y * d1 * d1);
    __half2 h1 = __floats2half2_rn(wv.z * d2 * d2, wv.w * d3 * d3);
    uint2 o;
    o.x = *reinterpret_cast<unsigned*>(&h0);
    o.y = *reinterpret_cast<unsigned*>(&h1);
    return o;
}

// Branch-free candidate test: single predicated RED, no BSSY/BSYNC.
__device__ __forceinline__ void test_red(unsigned h, unsigned thr) {
    asm volatile(
        "{\n\t"
        ".reg .pred p;\n\t"
        "setp.ge.u32 p, %0, %1;\n\t"
        "@p red.global.add.u32 [%2], 1;\n\t"
        "}"
        :: "r"(h), "r"(thr), "l"(&g_hist64[h])
        : "memory");
}

// ---------------------------------------------------------------- K0: sample + select
// grid 148 x 256. Reads 512 tiles x 1KB x 3 streams = 6 MB (coalesced).
__global__ __launch_bounds__(256) void k_sample(
    const float4* __restrict__ p,
    const float4* __restrict__ t,
    const float4* __restrict__ w)
{
    if (blockIdx.x < 64)                               // zero hist64 (256 KB)
        reinterpret_cast<uint4*>(g_hist64)[blockIdx.x * 256 + threadIdx.x] =
            make_uint4(0, 0, 0, 0);

    unsigned* hist = g_shist[blockIdx.x & (NREP - 1)];

    // 1/64 cluster sample: tile j covers float4s [j*16384, j*16384+256)
    for (int tile = blockIdx.x; tile < NTILES; tile += gridDim.x) {
        const int f = tile * 16384 + threadIdx.x;
        float4 pv = __ldg(p + f), tv = __ldg(t + f), wv = __ldg(w + f);
        uint2 o = loss4(pv, tv, wv);
        atomicAdd(&hist[(o.x & 0xFFFFu) >> 4], 1u);    // all 4 elements counted
        atomicAdd(&hist[ o.x >> 20        ], 1u);
        atomicAdd(&hist[(o.y & 0xFFFFu) >> 4], 1u);
        atomicAdd(&hist[ o.y >> 20        ], 1u);
    }

    // ---- last-block election ----
    __shared__ bool s_last;
    __syncthreads();
    if (threadIdx.x == 0) {
        __threadfence();
        s_last = (atomicAdd(&g_ticketA, 1u) == gridDim.x - 1u);
    }
    __syncthreads();
    if (!s_last) return;
    __threadfence();

    // ---- fused select (256 threads): conservative threshold T0 from sample ----
    __shared__ unsigned chunk[256];
    const int t0 = threadIdx.x;
    unsigned bl[16];
    #pragma unroll
    for (int j = 0; j < 16; j++) bl[j] = 0u;
    #pragma unroll
    for (int r = 0; r < NREP; r++) {
        const uint4* row = reinterpret_cast<const uint4*>(&g_shist[r][t0 * 16]);
        #pragma unroll
        for (int q = 0; q < 4; q++) {
            uint4 v = row[q];
            bl[q*4+0] += v.x; bl[q*4+1] += v.y; bl[q*4+2] += v.z; bl[q*4+3] += v.w;
        }
    }
    #pragma unroll
    for (int r = 0; r < NREP; r++) {                  // self-clean sample hist
        uint4* row = reinterpret_cast<uint4*>(&g_shist[r][t0 * 16]);
        #pragma unroll
        for (int q = 0; q < 4; q++) row[q] = make_uint4(0, 0, 0, 0);
    }
    unsigned csum = 0;
    #pragma unroll
    for (int j = 0; j < 16; j++) csum += bl[j];
    chunk[t0] = csum;
    __syncthreads();
    for (int d = 1; d < 256; d <<= 1) {               // suffix scan over chunks
        unsigned v = chunk[t0];
        if (t0 + d < 256) v += chunk[t0 + d];
        __syncthreads();
        chunk[t0] = v;
        __syncthreads();
    }
    const unsigned TGT = (K_KEPT + MARGIN + 63u) / 64u;   // sampled-count target
    unsigned sufnext = (t0 < 255) ? chunk[t0 + 1] : 0u;
    if (chunk[t0] >= TGT && sufnext < TGT) {
        unsigned cum = sufnext, T0v = 0;
        for (int b = 15; b >= 0; b--) {
            cum += bl[b];
            if (cum >= TGT) { T0v = ((unsigned)(t0 * 16 + b)) << 4; break; }
        }
        g_T0 = T0v;
        g_ticketA = 0u;                               // reset for next replay
    }
}

// ---------------------------------------------------------------- K1: full pass (+fused finalize)
// grid MUST be 1024 x 256: N4/(4*T) == 8 exact trips, lane-consecutive indices.
__global__ __launch_bounds__(256) void k_main(
    const float4* __restrict__ p,
    const float4* __restrict__ t,
    const float4* __restrict__ w,
    float* __restrict__ out)
{
    const unsigned thr = g_T0;
    const int T = gridDim.x * blockDim.x;             // 262144

    #define TESTW(u) do {                                                       \
        test_red((u) & 0xFFFFu, thr);                                           \
        test_red((u) >> 16,     thr);                                           \
    } while (0)

    for (int f = blockIdx.x * blockDim.x + threadIdx.x; f < N4; f += 4 * T) {
        const int f1 = f + T, f2 = f + 2 * T, f3 = f + 3 * T;
        // 12 independent, perfectly-coalesced LDG.128 (evict-first)
        float4 pa = __ldcs(p + f),  ta = __ldcs(t + f),  wa = __ldcs(w + f);
        float4 pb = __ldcs(p + f1), tb = __ldcs(t + f1), wb = __ldcs(w + f1);
        float4 pc = __ldcs(p + f2), tc = __ldcs(t + f2), wc = __ldcs(w + f2);
        float4 pd = __ldcs(p + f3), td = __ldcs(t + f3), wd = __ldcs(w + f3);

        uint2 oa = loss4(pa, ta, wa);
        uint2 ob = loss4(pb, tb, wb);
        uint2 oc = loss4(pc, tc, wc);
        uint2 od = loss4(pd, td, wd);
        TESTW(oa.x); TESTW(oa.y);
        TESTW(ob.x); TESTW(ob.y);
        TESTW(oc.x); TESTW(oc.y);
        TESTW(od.x); TESTW(od.y);
    }
    #undef TESTW

    // ---- last-block election ----
    __shared__ bool s_last;
    __syncthreads();
    if (threadIdx.x == 0) {
        __threadfence();
        s_last = (atomicAdd(&g_ticketB, 1u) == gridDim.x - 1u);
    }
    __syncthreads();
    if (!s_last) return;
    __threadfence();

    // ---- fused finalize (256 threads, fp32, all L2-hot) ----
    __shared__ unsigned sc[256];
    __shared__ float    sw[256];
    __shared__ int      s_chunk;
    __shared__ unsigned s_ac;
    __shared__ float    s_aw;
    const int tx = threadIdx.x;
    const uint4* h4 = reinterpret_cast<const uint4*>(g_hist64);

    unsigned cnt = 0; float ws = 0.0f;                // thread tx: bins [256tx, 256tx+256)
    #pragma unroll 8
    for (int jj = 0; jj < 64; jj++) {
        uint4 v = h4[tx * 64 + jj];
        int b = tx * 256 + jj * 4;
        cnt += v.x + v.y + v.z + v.w;
        if (v.x) ws += (float)v.x * bin_valf(b + 0);
        if (v.y) ws += (float)v.y * bin_valf(b + 1);
        if (v.z) ws += (float)v.z * bin_valf(b + 2);
        if (v.w) ws += (float)v.w * bin_valf(b + 3);
    }
    sc[tx] = cnt; sw[tx] = ws;
    if (tx == 0) s_chunk = -1;
    __syncthreads();
    for (int d = 1; d < 256; d <<= 1) {               // suffix scan over 256 chunks
        unsigned cx = sc[tx]; float xx = sw[tx];
        if (tx + d < 256) { cx += sc[tx + d]; xx += sw[tx + d]; }
        __syncthreads();
        sc[tx] = cx; sw[tx] = xx;
        __syncthreads();
    }
    unsigned cn = (tx < 255) ? sc[tx + 1] : 0u;
    float    wn = (tx < 255) ? sw[tx + 1] : 0.0f;
    if (sc[tx] >= K_KEPT && cn < K_KEPT) { s_chunk = tx; s_ac = cn; s_aw = wn; }
    __syncthreads();

    const int chunk = s_chunk;
    if (chunk < 0) {                                  // margin failure (~9-sigma; ~never)
        if (tx == 0) {
            float acc = sw[0] + (float)(K_KEPT - sc[0]) * bin_valf((int)thr);
            out[0] = acc / 8796093022208.0f;          // / 2^43
        }
    } else {
        __syncthreads();
        unsigned bc = g_hist64[chunk * 256 + tx];     // L2-hot
        sc[tx] = bc;
        sw[tx] = bc ? (float)bc * bin_valf(chunk * 256 + tx) : 0.0f;
        __syncthreads();
        for (int d = 1; d < 256; d <<= 1) {           // suffix scan within chunk
            unsigned cx = sc[tx]; float xx = sw[tx];
            if (tx + d < 256) { cx += sc[tx + d]; xx += sw[tx + d]; }
            __syncthreads();
            sc[tx] = cx; sw[tx] = xx;
            __syncthreads();
        }
        unsigned bn = (tx < 255) ? sc[tx + 1] : 0u;
        float    bw = (tx < 255) ? sw[tx + 1] : 0.0f;
        unsigned above = s_ac + bn;
        if (s_ac + sc[tx] >= K_KEPT && above < K_KEPT) {
            unsigned r = K_KEPT - above;
            float acc = s_aw + bw + (float)r * bin_valf(chunk * 256 + tx);
            out[0] = acc / 8796093022208.0f;          // / (2^25 * 2^18)
        }
    }
    if (tx == 0) g_ticketB = 0u;                      // reset for next replay
}

// ---------------------------------------------------------------- launch
extern "C" void kernel_launch(void* const* d_in, const int* in_sizes, int n_in,
                              void* d_out, int out_size) {
    const float4* p = (const float4*)d_in[0];   // predict
    const float4* t = (const float4*)d_in[1];   // target
    const float4* w = (const float4*)d_in[2];   // weight
    float* out = (float*)d_out;

    k_sample<<<148, 256>>>(p, t, w);        // 6 MB sample -> T0
    k_main  <<<1024, 256>>>(p, t, w, out);  // grid MUST stay 1024 (exact trips)
}